// round 2
// baseline (speedup 1.0000x reference)
#include <cuda_runtime.h>

#define NPATCH 196
#define NTHREADS 224

// CNOT: for amplitudes with ctrl bit set, flip target bit (register rename; free after unroll)
#define CNOT(cw, tw) { \
    const int cb = 1 << (3 - (cw)), tb = 1 << (3 - (tw)); \
    _Pragma("unroll") \
    for (int i = 0; i < 16; i++) { \
        if ((i & cb) && !(i & tb)) { float tmp = st[i]; st[i] = st[i | tb]; st[i | tb] = tmp; } \
    } }

// Ry on wire w with cos/sin of half-angle
#define RYW(w, cv, sv) { \
    const int bb = 1 << (3 - (w)); \
    _Pragma("unroll") \
    for (int i = 0; i < 16; i++) { \
        if (!(i & bb)) { \
            float a0 = st[i], a1 = st[i | bb]; \
            st[i]      = (cv) * a0 - (sv) * a1; \
            st[i | bb] = (sv) * a0 + (cv) * a1; \
        } \
    } }

__global__ __launch_bounds__(NTHREADS)
void quanv_kernel(const float* __restrict__ x,
                  const float* __restrict__ params,
                  const float* __restrict__ W,
                  const float* __restrict__ bias,
                  float* __restrict__ out)
{
    __shared__ float img[784];
    __shared__ float p0s[4];            // layer-0 raw params (fused into encoding angle)
    __shared__ float c2s[4], s2s[4];    // layer-1 cos/sin of half-angle
    __shared__ float slogits[10];

    const int b = blockIdx.x;
    const int t = threadIdx.x;

    // Cooperative vectorized image load: 196 x float4 = 784 floats
    if (t < NPATCH) {
        reinterpret_cast<float4*>(img)[t] =
            reinterpret_cast<const float4*>(x + b * 784)[t];
    }
    if (t < 4) {
        p0s[t] = params[t];
        float sv, cv;
        __sincosf(params[4 + t] * 0.5f, &sv, &cv);
        c2s[t] = cv; s2s[t] = sv;
    }
    if (t < 10) slogits[t] = bias[t];
    __syncthreads();

    if (t < NPATCH) {
        const int pr = t / 14, pc = t % 14;
        const float* base = img + (2 * pr) * 28 + 2 * pc;
        // angle order k = a*2 + c : (row offset a, col offset c); 8B-aligned pairs
        const float2 r0 = *reinterpret_cast<const float2*>(base);
        const float2 r1 = *reinterpret_cast<const float2*>(base + 28);

        float cc[4], ss[4];
        __sincosf((r0.x + p0s[0]) * 0.5f, &ss[0], &cc[0]);
        __sincosf((r0.y + p0s[1]) * 0.5f, &ss[1], &cc[1]);
        __sincosf((r1.x + p0s[2]) * 0.5f, &ss[2], &cc[2]);
        __sincosf((r1.y + p0s[3]) * 0.5f, &ss[3], &cc[3]);

        // Product state after encoding + layer-0 Rys (fused): idx = q0<<3 | q1<<2 | q2<<1 | q3
        float a01[4] = { cc[0]*cc[1], cc[0]*ss[1], ss[0]*cc[1], ss[0]*ss[1] };
        float a23[4] = { cc[2]*cc[3], cc[2]*ss[3], ss[2]*cc[3], ss[2]*ss[3] };
        float st[16];
        #pragma unroll
        for (int u = 0; u < 4; u++) {
            #pragma unroll
            for (int v = 0; v < 4; v++) st[u * 4 + v] = a01[u] * a23[v];
        }

        // layer 0 entanglers
        CNOT(0, 1); CNOT(1, 2); CNOT(2, 3); CNOT(3, 0);
        // layer 1 rotations
        RYW(0, c2s[0], s2s[0]);
        RYW(1, c2s[1], s2s[1]);
        RYW(2, c2s[2], s2s[2]);
        RYW(3, c2s[3], s2s[3]);
        // layer 1 entanglers
        CNOT(0, 1); CNOT(1, 2); CNOT(2, 3); CNOT(3, 0);

        // Measurement: PauliZ expvals via signed butterfly over probabilities
        float pp[16];
        #pragma unroll
        for (int i = 0; i < 16; i++) pp[i] = st[i] * st[i];

        float ap[8], am[8];
        #pragma unroll
        for (int j = 0; j < 8; j++) { ap[j] = pp[2*j] + pp[2*j+1]; am[j] = pp[2*j] - pp[2*j+1]; }
        float z3 = ((am[0] + am[1]) + (am[2] + am[3])) + ((am[4] + am[5]) + (am[6] + am[7]));

        float bp[4], bm[4];
        #pragma unroll
        for (int k = 0; k < 4; k++) { bp[k] = ap[2*k] + ap[2*k+1]; bm[k] = ap[2*k] - ap[2*k+1]; }
        float z2 = (bm[0] + bm[1]) + (bm[2] + bm[3]);

        float cp0 = bp[0] + bp[1], cp1 = bp[2] + bp[3];
        float z1 = (bp[0] - bp[1]) + (bp[2] - bp[3]);
        float z0 = cp0 - cp1;

        // Per-patch linear partials, accumulated via no-return shared atomics (REDS).
        // feat f = 4*t + wire; W row-major [10, 784]
        #pragma unroll
        for (int c = 0; c < 10; c++) {
            const float4 wv = *reinterpret_cast<const float4*>(W + c * 784 + 4 * t);
            float v = fmaf(z0, wv.x, fmaf(z1, wv.y, fmaf(z2, wv.z, z3 * wv.w)));
            atomicAdd(&slogits[c], v);
        }
    }
    __syncthreads();

    if (t < 10) {
        float m = slogits[0];
        #pragma unroll
        for (int c = 1; c < 10; c++) m = fmaxf(m, slogits[c]);
        float se = 0.0f;
        #pragma unroll
        for (int c = 0; c < 10; c++) se += __expf(slogits[c] - m);
        out[b * 10 + t] = slogits[t] - m - __logf(se);
    }
}

extern "C" void kernel_launch(void* const* d_in, const int* in_sizes, int n_in,
                              void* d_out, int out_size) {
    const float* x      = (const float*)d_in[0];   // [8192, 28, 28]
    const float* params = (const float*)d_in[1];   // [2, 4]
    const float* W      = (const float*)d_in[2];   // [10, 784]
    const float* bias   = (const float*)d_in[3];   // [10]
    float* out          = (float*)d_out;           // [8192, 10]

    const int B = in_sizes[0] / 784;
    quanv_kernel<<<B, NTHREADS>>>(x, params, W, bias, out);
}

// round 3
// speedup vs baseline: 10.7843x; 10.7843x over previous
#include <cuda_runtime.h>

#define NPATCH 196
#define NTHREADS 224

// CNOT: for amplitudes with ctrl bit set, flip target bit (register rename; free after unroll)
#define CNOT(cw, tw) { \
    const int cb = 1 << (3 - (cw)), tb = 1 << (3 - (tw)); \
    _Pragma("unroll") \
    for (int i = 0; i < 16; i++) { \
        if ((i & cb) && !(i & tb)) { float tmp = st[i]; st[i] = st[i | tb]; st[i | tb] = tmp; } \
    } }

// Ry on wire w with cos/sin of half-angle
#define RYW(w, cv, sv) { \
    const int bb = 1 << (3 - (w)); \
    _Pragma("unroll") \
    for (int i = 0; i < 16; i++) { \
        if (!(i & bb)) { \
            float a0 = st[i], a1 = st[i | bb]; \
            st[i]      = (cv) * a0 - (sv) * a1; \
            st[i | bb] = (sv) * a0 + (cv) * a1; \
        } \
    } }

__global__ __launch_bounds__(NTHREADS)
void quanv_kernel(const float* __restrict__ x,
                  const float* __restrict__ params,
                  const float* __restrict__ W,
                  const float* __restrict__ bias,
                  float* __restrict__ out)
{
    __shared__ float img[784];
    __shared__ float p0s[4];            // layer-0 raw params (fused into encoding angle)
    __shared__ float c2s[4], s2s[4];    // layer-1 cos/sin of half-angle
    __shared__ float wsum[7][10];
    __shared__ float slogits[10];

    const int b = blockIdx.x;
    const int t = threadIdx.x;
    const int lane = t & 31;

    // Cooperative vectorized image load: 196 x float4 = 784 floats
    if (t < NPATCH) {
        reinterpret_cast<float4*>(img)[t] =
            reinterpret_cast<const float4*>(x + b * 784)[t];
    }
    if (t < 4) {
        p0s[t] = params[t];
        float sv, cv;
        __sincosf(params[4 + t] * 0.5f, &sv, &cv);
        c2s[t] = cv; s2s[t] = sv;
    }
    __syncthreads();

    float vals[16];
    #pragma unroll
    for (int c = 0; c < 16; c++) vals[c] = 0.0f;

    if (t < NPATCH) {
        const int pr = t / 14, pc = t % 14;
        const float* base = img + (2 * pr) * 28 + 2 * pc;
        // angle order k = a*2 + c : (row offset a, col offset c); 8B-aligned pairs
        const float2 r0 = *reinterpret_cast<const float2*>(base);
        const float2 r1 = *reinterpret_cast<const float2*>(base + 28);

        float cc[4], ss[4];
        __sincosf((r0.x + p0s[0]) * 0.5f, &ss[0], &cc[0]);
        __sincosf((r0.y + p0s[1]) * 0.5f, &ss[1], &cc[1]);
        __sincosf((r1.x + p0s[2]) * 0.5f, &ss[2], &cc[2]);
        __sincosf((r1.y + p0s[3]) * 0.5f, &ss[3], &cc[3]);

        // Product state after encoding + layer-0 Rys (fused): idx = q0<<3 | q1<<2 | q2<<1 | q3
        float a01[4] = { cc[0]*cc[1], cc[0]*ss[1], ss[0]*cc[1], ss[0]*ss[1] };
        float a23[4] = { cc[2]*cc[3], cc[2]*ss[3], ss[2]*cc[3], ss[2]*ss[3] };
        float st[16];
        #pragma unroll
        for (int u = 0; u < 4; u++) {
            #pragma unroll
            for (int v = 0; v < 4; v++) st[u * 4 + v] = a01[u] * a23[v];
        }

        // layer 0 entanglers
        CNOT(0, 1); CNOT(1, 2); CNOT(2, 3); CNOT(3, 0);
        // layer 1 rotations
        RYW(0, c2s[0], s2s[0]);
        RYW(1, c2s[1], s2s[1]);
        RYW(2, c2s[2], s2s[2]);
        RYW(3, c2s[3], s2s[3]);
        // layer 1 entanglers
        CNOT(0, 1); CNOT(1, 2); CNOT(2, 3); CNOT(3, 0);

        // Measurement: PauliZ expvals via signed butterfly over probabilities
        float pp[16];
        #pragma unroll
        for (int i = 0; i < 16; i++) pp[i] = st[i] * st[i];

        float ap[8], am[8];
        #pragma unroll
        for (int j = 0; j < 8; j++) { ap[j] = pp[2*j] + pp[2*j+1]; am[j] = pp[2*j] - pp[2*j+1]; }
        float z3 = ((am[0] + am[1]) + (am[2] + am[3])) + ((am[4] + am[5]) + (am[6] + am[7]));

        float bp[4], bm[4];
        #pragma unroll
        for (int k = 0; k < 4; k++) { bp[k] = ap[2*k] + ap[2*k+1]; bm[k] = ap[2*k] - ap[2*k+1]; }
        float z2 = (bm[0] + bm[1]) + (bm[2] + bm[3]);

        float cp0 = bp[0] + bp[1], cp1 = bp[2] + bp[3];
        float z1 = (bp[0] - bp[1]) + (bp[2] - bp[3]);
        float z0 = cp0 - cp1;

        // Per-patch linear partials: feat f = 4*t + wire; W row-major [10, 784]
        #pragma unroll
        for (int c = 0; c < 10; c++) {
            const float4 wv = *reinterpret_cast<const float4*>(W + c * 784 + 4 * t);
            vals[c] = fmaf(z0, wv.x, fmaf(z1, wv.y, fmaf(z2, wv.z, z3 * wv.w)));
        }
    }

    // Multi-value butterfly: split the class set each stage.
    // After stages m=1,2,4,8 lane l holds the 16-lane sum of class bitrev4(l&15).
    #pragma unroll
    for (int stage = 0; stage < 4; stage++) {
        const int m = 1 << stage;
        const int h = 8 >> stage;
        const bool hi = (lane & m) != 0;
        #pragma unroll
        for (int c = 0; c < h; c++) {
            float send = hi ? vals[c]     : vals[c + h];
            float keep = hi ? vals[c + h] : vals[c];
            vals[c] = keep + __shfl_xor_sync(0xffffffffu, send, m);
        }
    }
    vals[0] += __shfl_xor_sync(0xffffffffu, vals[0], 16);

    const int cls = __brev(lane) >> 28;   // bitrev4 of lane&15
    if (lane < 16 && cls < 10) wsum[t >> 5][cls] = vals[0];
    __syncthreads();

    if (t < 10) {
        float v = bias[t];
        #pragma unroll
        for (int w = 0; w < 7; w++) v += wsum[w][t];
        slogits[t] = v;
    }
    __syncthreads();

    if (t < 10) {
        float m = slogits[0];
        #pragma unroll
        for (int c = 1; c < 10; c++) m = fmaxf(m, slogits[c]);
        float se = 0.0f;
        #pragma unroll
        for (int c = 0; c < 10; c++) se += __expf(slogits[c] - m);
        out[b * 10 + t] = slogits[t] - m - __logf(se);
    }
}

extern "C" void kernel_launch(void* const* d_in, const int* in_sizes, int n_in,
                              void* d_out, int out_size) {
    const float* x      = (const float*)d_in[0];   // [8192, 28, 28]
    const float* params = (const float*)d_in[1];   // [2, 4]
    const float* W      = (const float*)d_in[2];   // [10, 784]
    const float* bias   = (const float*)d_in[3];   // [10]
    float* out          = (float*)d_out;           // [8192, 10]

    const int B = in_sizes[0] / 784;
    quanv_kernel<<<B, NTHREADS>>>(x, params, W, bias, out);
}

// round 4
// speedup vs baseline: 11.7398x; 1.0886x over previous
#include <cuda_runtime.h>

#define NPATCH 196
#define NTHREADS 224

typedef unsigned long long u64;

__device__ __forceinline__ u64 mul2(u64 a, u64 b) {
    u64 d; asm("mul.rn.f32x2 %0,%1,%2;" : "=l"(d) : "l"(a), "l"(b)); return d;
}
__device__ __forceinline__ u64 fma2(u64 a, u64 b, u64 c) {
    u64 d; asm("fma.rn.f32x2 %0,%1,%2,%3;" : "=l"(d) : "l"(a), "l"(b), "l"(c)); return d;
}
__device__ __forceinline__ u64 pk2(float lo, float hi) {
    u64 d; asm("mov.b64 %0,{%1,%2};" : "=l"(d) : "f"(lo), "f"(hi)); return d;
}
__device__ __forceinline__ void upk(u64 v, float& lo, float& hi) {
    asm("mov.b64 {%0,%1},%2;" : "=f"(lo), "=f"(hi) : "l"(v));
}

// CNOT on scalar state: register rename after unroll (zero SASS)
#define CNOT(cw, tw) { \
    const int cb = 1 << (3 - (cw)), tb = 1 << (3 - (tw)); \
    _Pragma("unroll") \
    for (int i = 0; i < 16; i++) { \
        if ((i & cb) && !(i & tb)) { float tmp = st[i]; st[i] = st[i | tb]; st[i | tb] = tmp; } \
    } }

// Packed Ry on wire w (w in {0,1,2}); kb = pack-index bit distance
#define RYWP(kb, cv, sv, nsv) { \
    _Pragma("unroll") \
    for (int k = 0; k < 8; k++) { \
        if (!(k & (kb))) { \
            u64 a0 = P[k], a1 = P[k | (kb)]; \
            P[k]        = fma2((nsv), a1, mul2((cv), a0)); \
            P[k | (kb)] = fma2((cv),  a1, mul2((sv), a0)); \
        } \
    } }

__global__ __launch_bounds__(NTHREADS)
void quanv_kernel(const float* __restrict__ x,
                  const float* __restrict__ params,
                  const float* __restrict__ W,
                  const float* __restrict__ bias,
                  float* __restrict__ out)
{
    __shared__ float img[784];
    __shared__ float p0s[4];            // layer-0 raw params (fused into encoding angle)
    __shared__ u64  cP[3], sP[3], nsP[3];   // packed (c,c),(s,s),(-s,-s) for wires 0-2
    __shared__ float c3s, s3s;              // wire-3 layer-1 scalars
    __shared__ float wsum[7][10];
    __shared__ float slogits[10];

    const int b = blockIdx.x;
    const int t = threadIdx.x;
    const int lane = t & 31;

    // Cooperative vectorized image load: 196 x float4 = 784 floats
    if (t < NPATCH) {
        reinterpret_cast<float4*>(img)[t] =
            reinterpret_cast<const float4*>(x + b * 784)[t];
    }
    if (t < 4) {
        p0s[t] = params[t];
        float sv, cv;
        __sincosf(params[4 + t] * 0.5f, &sv, &cv);
        if (t < 3) { cP[t] = pk2(cv, cv); sP[t] = pk2(sv, sv); nsP[t] = pk2(-sv, -sv); }
        else       { c3s = cv; s3s = sv; }
    }
    __syncthreads();

    float vals[16];
    #pragma unroll
    for (int c = 0; c < 16; c++) vals[c] = 0.0f;

    if (t < NPATCH) {
        const int pr = t / 14, pc = t % 14;
        const float* base = img + (2 * pr) * 28 + 2 * pc;
        const float2 r0 = *reinterpret_cast<const float2*>(base);
        const float2 r1 = *reinterpret_cast<const float2*>(base + 28);

        float cc[4], ss[4];
        __sincosf((r0.x + p0s[0]) * 0.5f, &ss[0], &cc[0]);
        __sincosf((r0.y + p0s[1]) * 0.5f, &ss[1], &cc[1]);
        __sincosf((r1.x + p0s[2]) * 0.5f, &ss[2], &cc[2]);
        __sincosf((r1.y + p0s[3]) * 0.5f, &ss[3], &cc[3]);

        // Product state after encoding + fused layer-0 Rys: idx = q0<<3|q1<<2|q2<<1|q3
        float a01[4] = { cc[0]*cc[1], cc[0]*ss[1], ss[0]*cc[1], ss[0]*ss[1] };
        float a23[4] = { cc[2]*cc[3], cc[2]*ss[3], ss[2]*cc[3], ss[2]*ss[3] };
        float st[16];
        #pragma unroll
        for (int u = 0; u < 4; u++) {
            #pragma unroll
            for (int v = 0; v < 4; v++) st[u * 4 + v] = a01[u] * a23[v];
        }

        // layer-0 entanglers (renames)
        CNOT(0, 1); CNOT(1, 2); CNOT(2, 3); CNOT(3, 0);

        // Pack along wire 3: P[k] = (st[2k], st[2k+1])
        u64 P[8];
        #pragma unroll
        for (int k = 0; k < 8; k++) P[k] = pk2(st[2*k], st[2*k+1]);

        // layer-1 Ry on wires 0,1,2 — packed (elementwise on pairs)
        {
            const u64 c0 = cP[0], s0 = sP[0], n0 = nsP[0];
            const u64 c1 = cP[1], s1 = sP[1], n1 = nsP[1];
            const u64 c2 = cP[2], s2 = sP[2], n2 = nsP[2];
            RYWP(4, c0, s0, n0);
            RYWP(2, c1, s1, n1);
            RYWP(1, c2, s2, n2);
        }

        // Unpack; layer-1 Ry on wire 3 — scalar (mixes within packs)
        #pragma unroll
        for (int k = 0; k < 8; k++) upk(P[k], st[2*k], st[2*k+1]);
        {
            const float cv = c3s, sv = s3s;
            #pragma unroll
            for (int i = 0; i < 16; i += 2) {
                float a0 = st[i], a1 = st[i + 1];
                st[i]     = cv * a0 - sv * a1;
                st[i + 1] = sv * a0 + cv * a1;
            }
        }

        // layer-1 entanglers (renames)
        CNOT(0, 1); CNOT(1, 2); CNOT(2, 3); CNOT(3, 0);

        // Measurement: PauliZ expvals via signed butterfly over probabilities
        float pp[16];
        #pragma unroll
        for (int i = 0; i < 16; i++) pp[i] = st[i] * st[i];

        float ap[8], am[8];
        #pragma unroll
        for (int j = 0; j < 8; j++) { ap[j] = pp[2*j] + pp[2*j+1]; am[j] = pp[2*j] - pp[2*j+1]; }
        float z3 = ((am[0] + am[1]) + (am[2] + am[3])) + ((am[4] + am[5]) + (am[6] + am[7]));

        float bp[4], bm[4];
        #pragma unroll
        for (int k = 0; k < 4; k++) { bp[k] = ap[2*k] + ap[2*k+1]; bm[k] = ap[2*k] - ap[2*k+1]; }
        float z2 = (bm[0] + bm[1]) + (bm[2] + bm[3]);

        float cp0 = bp[0] + bp[1], cp1 = bp[2] + bp[3];
        float z1 = (bp[0] - bp[1]) + (bp[2] - bp[3]);
        float z0 = cp0 - cp1;

        // Per-patch linear partials, packed: feat f = 4*t + wire; W row-major [10,784]
        const u64 z01 = pk2(z0, z1), z23 = pk2(z2, z3);
        #pragma unroll
        for (int c = 0; c < 10; c++) {
            u64 w01, w23;
            asm("ld.global.nc.v2.b64 {%0,%1},[%2];"
                : "=l"(w01), "=l"(w23)
                : "l"(W + c * 784 + 4 * t));
            u64 acc = fma2(z23, w23, mul2(z01, w01));
            float alo, ahi; upk(acc, alo, ahi);
            vals[c] = alo + ahi;
        }
    }

    // Multi-value butterfly: split the class set each stage.
    #pragma unroll
    for (int stage = 0; stage < 4; stage++) {
        const int m = 1 << stage;
        const int h = 8 >> stage;
        const bool hi = (lane & m) != 0;
        #pragma unroll
        for (int c = 0; c < h; c++) {
            float send = hi ? vals[c]     : vals[c + h];
            float keep = hi ? vals[c + h] : vals[c];
            vals[c] = keep + __shfl_xor_sync(0xffffffffu, send, m);
        }
    }
    vals[0] += __shfl_xor_sync(0xffffffffu, vals[0], 16);

    const int cls = __brev(lane) >> 28;   // bitrev4 of lane&15
    if (lane < 16 && cls < 10) wsum[t >> 5][cls] = vals[0];
    __syncthreads();

    if (t < 10) {
        float v = bias[t];
        #pragma unroll
        for (int w = 0; w < 7; w++) v += wsum[w][t];
        slogits[t] = v;
    }
    __syncthreads();

    if (t < 10) {
        float m = slogits[0];
        #pragma unroll
        for (int c = 1; c < 10; c++) m = fmaxf(m, slogits[c]);
        float se = 0.0f;
        #pragma unroll
        for (int c = 0; c < 10; c++) se += __expf(slogits[c] - m);
        out[b * 10 + t] = slogits[t] - m - __logf(se);
    }
}

extern "C" void kernel_launch(void* const* d_in, const int* in_sizes, int n_in,
                              void* d_out, int out_size) {
    const float* x      = (const float*)d_in[0];   // [8192, 28, 28]
    const float* params = (const float*)d_in[1];   // [2, 4]
    const float* W      = (const float*)d_in[2];   // [10, 784]
    const float* bias   = (const float*)d_in[3];   // [10]
    float* out          = (float*)d_out;           // [8192, 10]

    const int B = in_sizes[0] / 784;
    quanv_kernel<<<B, NTHREADS>>>(x, params, W, bias, out);
}